// round 5
// baseline (speedup 1.0000x reference)
#include <cuda_runtime.h>
#include <math.h>

// ---------------------------------------------------------------------------
// WaveletF1DModule: 2-level sym2 DWT + truncated-DFT spectral conv (32 modes).
// B=32, N=512, M=512. row = b*512 + m. Signal lens: 257 (L0), 130 (L1).
// DFT GEMMs: tf32 mma.sync, 2-term split (3xTF32), register-split + dbl-buffer.
// ---------------------------------------------------------------------------

#define RTOT 16384
#define N1 257
#define N2 130
#define N1PF 288   // fwd stride (lo1/hi1), 9 k-tiles of 32
#define N2PF 160   // fwd stride (lo2/hi2), 5 k-tiles
#define N1PI 320   // inv out stride (ud0/us1), 5 n-tiles of 64
#define N2PI 192   // inv out stride (ud1/s2), 3 n-tiles

__device__ float g_lo1[RTOT * N1PF];
__device__ float g_hi1[RTOT * N1PF];
__device__ float g_lo2[RTOT * N2PF];
__device__ float g_hi2[RTOT * N2PF];
__device__ float g_xf[4][RTOT * 64];     // 0=lo1,1=hi1,2=lo2,3=hi2 (re[32]|im[32])
__device__ float g_spec[4][RTOT * 64];   // 0=Ud0,1=Us1,2=Ud1,3=S2 (a_k-scaled)
__device__ float g_ud0[RTOT * N1PI];
__device__ float g_us1[RTOT * N1PI];
__device__ float g_ud1[RTOT * N2PI];
__device__ float g_s2 [RTOT * N2PI];
__device__ float g_Bf257[N1PF * 64];     // pad rows stay zero
__device__ float g_Bi257[64 * N1PI];     // pad cols stay zero
__device__ float g_Bf130[N2PF * 64];
__device__ float g_Bi130[64 * N2PI];
__device__ float g_W[6 * 512 * 2048];    // [w][m][ri*1024 + j*32 + k]

#define G0 0.48296291314469025f
#define G1 0.836516303737469f
#define G2 0.22414386804185735f
#define G3 (-0.12940952255092145f)
#define H0 (-0.12940952255092145f)
#define H1 (-0.22414386804185735f)
#define H2 0.836516303737469f
#define H3 (-0.48296291314469025f)

__device__ __forceinline__ unsigned tf32_hi_bits(float v) {
    unsigned r;
    asm("cvt.rna.tf32.f32 %0, %1;" : "=r"(r) : "f"(v));
    return r;
}

__device__ __forceinline__ void mma_tf32(float c[4], const unsigned a[4], const unsigned b[2]) {
    asm volatile(
        "mma.sync.aligned.m16n8k8.row.col.f32.tf32.tf32.f32 "
        "{%0,%1,%2,%3}, {%4,%5,%6,%7}, {%8,%9}, {%0,%1,%2,%3};\n"
        : "+f"(c[0]), "+f"(c[1]), "+f"(c[2]), "+f"(c[3])
        : "r"(a[0]), "r"(a[1]), "r"(a[2]), "r"(a[3]), "r"(b[0]), "r"(b[1]));
}

// ---------------------------------------------------------------------------
__global__ void prep_basis() {
    int idx = blockIdx.x * blockDim.x + threadIdx.x;
    const double TWO_PI = 6.283185307179586476925286766559;
    if (idx < N1 * 64) {
        int t = idx / 64, c = idx % 64, k = c & 31;
        double th = TWO_PI * (double)(k * t) / 257.0;
        float v = (c < 32) ? (float)cos(th) : (float)(-sin(th));
        g_Bf257[t * 64 + c] = v;
        g_Bi257[c * N1PI + t] = v;
    }
    int idx2 = idx - N1 * 64;
    if (idx2 >= 0 && idx2 < N2 * 64) {
        int t = idx2 / 64, c = idx2 % 64, k = c & 31;
        double th = TWO_PI * (double)(k * t) / 130.0;
        float v = (c < 32) ? (float)cos(th) : (float)(-sin(th));
        g_Bf130[t * 64 + c] = v;
        g_Bi130[c * N2PI + t] = v;
    }
}

// ---------------------------------------------------------------------------
__global__ void pack_weights(const float* __restrict__ l0k0_r, const float* __restrict__ l0k0_i,
                             const float* __restrict__ l0k1_r, const float* __restrict__ l0k1_i,
                             const float* __restrict__ l0k2_r, const float* __restrict__ l0k2_i,
                             const float* __restrict__ l1k0_r, const float* __restrict__ l1k0_i,
                             const float* __restrict__ l1k1_r, const float* __restrict__ l1k1_i,
                             const float* __restrict__ l1k2_r, const float* __restrict__ l1k2_i,
                             const float* __restrict__ D_r,    const float* __restrict__ D_i) {
    int idx = blockIdx.x * blockDim.x + threadIdx.x;
    if (idx >= 512 * 1024) return;
    int m = idx >> 10, j = (idx >> 5) & 31, k = idx & 31;
    int dst = m * 2048 + j * 32 + k;
    int s86  = (m * 86 + j) * 86 + k;
    int s65  = (m * 65 + j) * 65 + k;
    int s132 = (m * 132 + j) * 132 + k;
    g_W[0 * 512 * 2048 + dst]        = l0k0_r[s86];
    g_W[0 * 512 * 2048 + dst + 1024] = l0k0_i[s86];
    g_W[1 * 512 * 2048 + dst]        = l0k1_r[s86];
    g_W[1 * 512 * 2048 + dst + 1024] = l0k1_i[s86];
    g_W[2 * 512 * 2048 + dst]        = l0k2_r[s86];
    g_W[2 * 512 * 2048 + dst + 1024] = l0k2_i[s86];
    g_W[3 * 512 * 2048 + dst]        = l1k0_r[s65];
    g_W[3 * 512 * 2048 + dst + 1024] = l1k0_i[s65];
    g_W[4 * 512 * 2048 + dst]        = l1k1_r[s65];
    g_W[4 * 512 * 2048 + dst + 1024] = l1k1_i[s65];
    g_W[5 * 512 * 2048 + dst]        = l1k2_r[s65] + D_r[s132];
    g_W[5 * 512 * 2048 + dst + 1024] = l1k2_i[s65] + D_i[s132];
}

// ---------------------------------------------------------------------------
// Fused dwt level0 + level1.
__global__ __launch_bounds__(256) void dwt_fused(const float* __restrict__ x) {
    extern __shared__ float dyn[];
    float* sx = dyn;                // 512*33
    float* sb = dyn + 512 * 33;     // 257*33
    int m0 = blockIdx.x * 32, b = blockIdx.y;
    int tid = threadIdx.x, lane = tid & 31, wid = tid >> 5;

    for (int i = tid; i < 512 * 32; i += 256) {
        int n = i >> 5, c = i & 31;
        sx[n * 33 + c] = x[(b * 512 + n) * 512 + m0 + c];
    }
    __syncthreads();
    for (int i = tid; i < 257 * 32; i += 256) {
        int t = i >> 5, c = i & 31, n = 2 * t - 2;
        float v[4];
        #pragma unroll
        for (int k = 0; k < 4; k++) {
            int nn = n + k; nn = nn < 0 ? -nn : (nn > 511 ? 1022 - nn : nn);
            v[k] = sx[nn * 33 + c];
        }
        sb[t * 33 + c] = H0 * v[0] + H1 * v[1] + H2 * v[2] + H3 * v[3];
    }
    __syncthreads();
    for (int c = wid; c < 32; c += 8) {
        int row = b * 512 + m0 + c;
        for (int t = lane; t < 257; t += 32) g_hi1[row * N1PF + t] = sb[t * 33 + c];
    }
    __syncthreads();
    for (int i = tid; i < 257 * 32; i += 256) {
        int t = i >> 5, c = i & 31, n = 2 * t - 2;
        float v[4];
        #pragma unroll
        for (int k = 0; k < 4; k++) {
            int nn = n + k; nn = nn < 0 ? -nn : (nn > 511 ? 1022 - nn : nn);
            v[k] = sx[nn * 33 + c];
        }
        sb[t * 33 + c] = G0 * v[0] + G1 * v[1] + G2 * v[2] + G3 * v[3];
    }
    __syncthreads();
    float* s2lo = sx;
    float* s2hi = sx + 130 * 33;
    for (int c = wid; c < 32; c += 8) {
        int row = b * 512 + m0 + c;
        for (int t = lane; t < 257; t += 32) g_lo1[row * N1PF + t] = sb[t * 33 + c];
    }
    for (int i = tid; i < 130 * 32; i += 256) {
        int t = i >> 5, c = i & 31, n = 2 * t - 2;
        float v[4];
        #pragma unroll
        for (int k = 0; k < 4; k++) {
            int nn = n + k; nn = nn < 0 ? -nn : (nn > 256 ? 512 - nn : nn);
            v[k] = sb[nn * 33 + c];
        }
        s2lo[t * 33 + c] = G0 * v[0] + G1 * v[1] + G2 * v[2] + G3 * v[3];
        s2hi[t * 33 + c] = H0 * v[0] + H1 * v[1] + H2 * v[2] + H3 * v[3];
    }
    __syncthreads();
    for (int c = wid; c < 32; c += 8) {
        int row = b * 512 + m0 + c;
        for (int t = lane; t < 130; t += 32) {
            g_lo2[row * N2PF + t] = s2lo[t * 33 + c];
            g_hi2[row * N2PF + t] = s2hi[t * 33 + c];
        }
    }
}

// ---------------------------------------------------------------------------
// tf32 split GEMM core v2: fp32 smem staging, register hi/lo split,
// double-buffered k-tiles with register prefetch (1 sync per k-tile).
__device__ __forceinline__ void gemm_tf32_core(
    const float* __restrict__ A, int lda, int kit,
    const float* __restrict__ B, int ldb, int bn0,
    float* __restrict__ C, int ldc, int cn0, int row0)
{
    extern __shared__ float smem[];
    float* As0 = smem;                    // 128*36
    float* As1 = smem + 128 * 36;
    float* Bs0 = smem + 2 * 128 * 36;     // 32*72
    float* Bs1 = Bs0 + 32 * 72;

    int tid = threadIdx.x, lane = tid & 31, wid = tid >> 5;
    int wm = wid >> 1, wn = wid & 1;
    int gr = lane >> 2, tg = lane & 3;

    int ar = tid >> 3, akq = (tid & 7) * 4;    // A-load coords (per 256-thread pass: 32 rows)
    int bkb = tid >> 4, bcq = (tid & 15) * 4;  // B-load coords (16 k-rows per pass)

    float acc[2][4][4] = {};
    float4 ra[4], rb[2];

    // tile 0 -> buf0
    #pragma unroll
    for (int it = 0; it < 4; it++)
        *(float4*)&As0[(ar + it * 32) * 36 + akq] = *(const float4*)&A[(row0 + ar + it * 32) * lda + akq];
    #pragma unroll
    for (int it = 0; it < 2; it++)
        *(float4*)&Bs0[(bkb + it * 16) * 72 + bcq] = *(const float4*)&B[(bkb + it * 16) * ldb + bn0 + bcq];
    // prefetch tile 1 into regs
    if (kit > 1) {
        #pragma unroll
        for (int it = 0; it < 4; it++)
            ra[it] = *(const float4*)&A[(row0 + ar + it * 32) * lda + 32 + akq];
        #pragma unroll
        for (int it = 0; it < 2; it++)
            rb[it] = *(const float4*)&B[(32 + bkb + it * 16) * ldb + bn0 + bcq];
    }
    __syncthreads();

    for (int kt = 0; kt < kit; kt++) {
        const float* Ac = (kt & 1) ? As1 : As0;
        const float* Bc = (kt & 1) ? Bs1 : Bs0;
        float* An = (kt & 1) ? As0 : As1;
        float* Bn = (kt & 1) ? Bs0 : Bs1;

        if (kt + 1 < kit) {
            // store prefetched tile kt+1 into the other buffer
            #pragma unroll
            for (int it = 0; it < 4; it++)
                *(float4*)&An[(ar + it * 32) * 36 + akq] = ra[it];
            #pragma unroll
            for (int it = 0; it < 2; it++)
                *(float4*)&Bn[(bkb + it * 16) * 72 + bcq] = rb[it];
            if (kt + 2 < kit) {
                int k0 = (kt + 2) * 32;
                #pragma unroll
                for (int it = 0; it < 4; it++)
                    ra[it] = *(const float4*)&A[(row0 + ar + it * 32) * lda + k0 + akq];
                #pragma unroll
                for (int it = 0; it < 2; it++)
                    rb[it] = *(const float4*)&B[(k0 + bkb + it * 16) * ldb + bn0 + bcq];
            }
        }

        #pragma unroll
        for (int k8 = 0; k8 < 32; k8 += 8) {
            unsigned ah[2][4], al[2][4], bh[4][2], bl[4][2];
            #pragma unroll
            for (int mt = 0; mt < 2; mt++) {
                int rbse = wm * 32 + mt * 16;
                float f0 = Ac[(rbse + gr) * 36 + k8 + tg];
                float f1 = Ac[(rbse + gr + 8) * 36 + k8 + tg];
                float f2 = Ac[(rbse + gr) * 36 + k8 + tg + 4];
                float f3 = Ac[(rbse + gr + 8) * 36 + k8 + tg + 4];
                ah[mt][0] = tf32_hi_bits(f0); al[mt][0] = __float_as_uint(f0 - __uint_as_float(ah[mt][0]));
                ah[mt][1] = tf32_hi_bits(f1); al[mt][1] = __float_as_uint(f1 - __uint_as_float(ah[mt][1]));
                ah[mt][2] = tf32_hi_bits(f2); al[mt][2] = __float_as_uint(f2 - __uint_as_float(ah[mt][2]));
                ah[mt][3] = tf32_hi_bits(f3); al[mt][3] = __float_as_uint(f3 - __uint_as_float(ah[mt][3]));
            }
            #pragma unroll
            for (int nt = 0; nt < 4; nt++) {
                int nb = wn * 32 + nt * 8 + gr;
                float g0 = Bc[(k8 + tg) * 72 + nb];
                float g1 = Bc[(k8 + tg + 4) * 72 + nb];
                bh[nt][0] = tf32_hi_bits(g0); bl[nt][0] = __float_as_uint(g0 - __uint_as_float(bh[nt][0]));
                bh[nt][1] = tf32_hi_bits(g1); bl[nt][1] = __float_as_uint(g1 - __uint_as_float(bh[nt][1]));
            }
            #pragma unroll
            for (int mt = 0; mt < 2; mt++)
                #pragma unroll
                for (int nt = 0; nt < 4; nt++) {
                    mma_tf32(acc[mt][nt], ah[mt], bh[nt]);
                    mma_tf32(acc[mt][nt], ah[mt], bl[nt]);
                    mma_tf32(acc[mt][nt], al[mt], bh[nt]);
                }
        }
        __syncthreads();
    }
    #pragma unroll
    for (int mt = 0; mt < 2; mt++)
        #pragma unroll
        for (int nt = 0; nt < 4; nt++) {
            int r = row0 + wm * 32 + mt * 16 + gr;
            int cc = cn0 + wn * 32 + nt * 8 + tg * 2;
            *(float2*)&C[r * ldc + cc]       = make_float2(acc[mt][nt][0], acc[mt][nt][1]);
            *(float2*)&C[(r + 8) * ldc + cc] = make_float2(acc[mt][nt][2], acc[mt][nt][3]);
        }
}

// Forward DFT: z = 0..3 -> lo1,hi1,lo2,hi2
__global__ __launch_bounds__(256) void fwd_gemm_tf32() {
    int z = blockIdx.z, row0 = blockIdx.y * 128;
    if (z == 0)      gemm_tf32_core(g_lo1, N1PF, 9, g_Bf257, 64, 0, &g_xf[0][0], 64, 0, row0);
    else if (z == 1) gemm_tf32_core(g_hi1, N1PF, 9, g_Bf257, 64, 0, &g_xf[1][0], 64, 0, row0);
    else if (z == 2) gemm_tf32_core(g_lo2, N2PF, 5, g_Bf130, 64, 0, &g_xf[2][0], 64, 0, row0);
    else             gemm_tf32_core(g_hi2, N2PF, 5, g_Bf130, 64, 0, &g_xf[3][0], 64, 0, row0);
}

// Inverse DFT
__global__ __launch_bounds__(256) void inv_gemm_tf32() {
    int xb = blockIdx.x, z = blockIdx.z, row0 = blockIdx.y * 128;
    if (xb < 5) {
        int n0 = xb * 64;
        if (z == 0) gemm_tf32_core(&g_spec[0][0], 64, 2, g_Bi257, N1PI, n0, g_ud0, N1PI, n0, row0);
        else        gemm_tf32_core(&g_spec[1][0], 64, 2, g_Bi257, N1PI, n0, g_us1, N1PI, n0, row0);
    } else {
        int n0 = (xb - 5) * 64;
        if (z == 0) gemm_tf32_core(&g_spec[2][0], 64, 2, g_Bi130, N2PI, n0, g_ud1, N2PI, n0, row0);
        else        gemm_tf32_core(&g_spec[3][0], 64, 2, g_Bi130, N2PI, n0, g_s2,  N2PI, n0, row0);
    }
}

// ---------------------------------------------------------------------------
struct MixAcc { float r00, r01, r10, r11, i00, i01, i10, i11; };

__device__ __forceinline__ void mix_zero(MixAcc& a) {
    a.r00 = a.r01 = a.r10 = a.r11 = 0.f;
    a.i00 = a.i01 = a.i10 = a.i11 = 0.f;
}

__device__ __forceinline__ void mix_pass(const float* __restrict__ sx,
                                         const float* __restrict__ sw,
                                         int b0, int k0, MixAcc& a) {
    #pragma unroll
    for (int j = 0; j < 32; j++) {
        float xr0 = sx[b0 * 64 + j],        xi0 = sx[b0 * 64 + 32 + j];
        float xr1 = sx[(b0 + 1) * 64 + j],  xi1 = sx[(b0 + 1) * 64 + 32 + j];
        float wr0 = sw[j * 32 + k0],        wr1 = sw[j * 32 + k0 + 1];
        float wi0 = sw[1024 + j * 32 + k0], wi1 = sw[1024 + j * 32 + k0 + 1];
        a.r00 += xr0 * wr0 - xi0 * wi0;  a.i00 += xr0 * wi0 + xi0 * wr0;
        a.r01 += xr0 * wr1 - xi0 * wi1;  a.i01 += xr0 * wi1 + xi0 * wr1;
        a.r10 += xr1 * wr0 - xi1 * wi0;  a.i10 += xr1 * wi0 + xi1 * wr0;
        a.r11 += xr1 * wr1 - xi1 * wi1;  a.i11 += xr1 * wi1 + xi1 * wr1;
    }
}

__device__ __forceinline__ void mix_store(float* __restrict__ dst, int m, int b0, int k0,
                                          const MixAcc& a, float invN) {
    float a0 = (k0 == 0 ? 1.f : 2.f) * invN;
    float a1 = 2.f * invN;
    int base0 = ((b0) * 512 + m) * 64 + k0;
    int base1 = ((b0 + 1) * 512 + m) * 64 + k0;
    dst[base0]      = a.r00 * a0;  dst[base0 + 1]  = a.r01 * a1;
    dst[base0 + 32] = a.i00 * a0;  dst[base0 + 33] = a.i01 * a1;
    dst[base1]      = a.r10 * a0;  dst[base1 + 1]  = a.r11 * a1;
    dst[base1 + 32] = a.i10 * a0;  dst[base1 + 33] = a.i11 * a1;
}

// All weights + spectra staged in 80KB smem, single sync.
__global__ __launch_bounds__(256) void mix_kernel() {
    extern __shared__ float sm[];
    float* sxf = sm;            // 4*2048
    float* sW  = sm + 8192;     // 6*2048
    int m = blockIdx.x, tid = threadIdx.x;
    #pragma unroll
    for (int s = 0; s < 4; s++)
        for (int i = tid; i < 2048; i += 256) {
            int b = i >> 6, c = i & 63;
            sxf[s * 2048 + i] = g_xf[s][(b * 512 + m) * 64 + c];
        }
    #pragma unroll
    for (int w = 0; w < 6; w++)
        for (int i = tid; i < 2048; i += 256)
            sW[w * 2048 + i] = g_W[w * 512 * 2048 + m * 2048 + i];
    __syncthreads();

    int b0 = (tid >> 4) * 2;
    int k0 = (tid & 15) * 2;

    MixAcc a;
    mix_zero(a);
    mix_pass(&sxf[1 * 2048], &sW[0 * 2048], b0, k0, a);
    mix_pass(&sxf[0 * 2048], &sW[1 * 2048], b0, k0, a);
    mix_store(g_spec[0], m, b0, k0, a, 1.0f / 257.0f);

    mix_zero(a);
    mix_pass(&sxf[0 * 2048], &sW[2 * 2048], b0, k0, a);
    mix_store(g_spec[1], m, b0, k0, a, 1.0f / 257.0f);

    mix_zero(a);
    mix_pass(&sxf[3 * 2048], &sW[3 * 2048], b0, k0, a);
    mix_pass(&sxf[2 * 2048], &sW[4 * 2048], b0, k0, a);
    mix_store(g_spec[2], m, b0, k0, a, 1.0f / 130.0f);

    mix_zero(a);
    mix_pass(&sxf[2 * 2048], &sW[5 * 2048], b0, k0, a);
    mix_store(g_spec[3], m, b0, k0, a, 1.0f / 130.0f);
}

// ---------------------------------------------------------------------------
// Fused idwt level1 + level0 + output transpose.
__global__ __launch_bounds__(256) void idwt_fused(float* __restrict__ out) {
    extern __shared__ float dyn[];
    float* yb  = dyn;                    // 258*33
    float* rlo = dyn + 258 * 33;         // 257*33
    float* rhi = rlo + 257 * 33;         // 257*33
    int m0 = blockIdx.x * 32, b = blockIdx.y;
    int tid = threadIdx.x, lane = tid & 31, wid = tid >> 5;

    for (int c = wid; c < 32; c += 8) {
        int row = b * 512 + m0 + c;
        for (int t = lane; t < 130; t += 32) {
            rlo[t * 33 + c] = g_s2[row * N2PI + t];
            rhi[t * 33 + c] = g_ud1[row * N2PI + t];
        }
    }
    __syncthreads();
    for (int i = tid; i < 258 * 32; i += 256) {
        int n = i >> 5, c = i & 31;
        float v;
        if (n & 1) {
            int i0 = (n - 1) >> 1, i1 = (n + 1) >> 1;
            v = rlo[i0 * 33 + c] * G3 + rhi[i0 * 33 + c] * H3
              + rlo[i1 * 33 + c] * G1 + rhi[i1 * 33 + c] * H1;
        } else {
            int i0 = n >> 1, i1 = i0 + 1;
            v = rlo[i0 * 33 + c] * G2 + rhi[i0 * 33 + c] * H2
              + rlo[i1 * 33 + c] * G0 + rhi[i1 * 33 + c] * H0;
        }
        yb[n * 33 + c] = v;
    }
    __syncthreads();
    for (int c = wid; c < 32; c += 8) {
        int row = b * 512 + m0 + c;
        for (int t = lane; t < 257; t += 32) {
            rlo[t * 33 + c] = yb[t * 33 + c] + g_us1[row * N1PI + t];
            rhi[t * 33 + c] = g_ud0[row * N1PI + t];
        }
    }
    __syncthreads();
    for (int i = tid; i < 512 * 32; i += 256) {
        int n = i >> 5, c = i & 31;
        float v;
        if (n & 1) {
            int i0 = (n - 1) >> 1, i1 = (n + 1) >> 1;
            v = rlo[i0 * 33 + c] * G3 + rhi[i0 * 33 + c] * H3
              + rlo[i1 * 33 + c] * G1 + rhi[i1 * 33 + c] * H1;
        } else {
            int i0 = n >> 1, i1 = i0 + 1;
            v = rlo[i0 * 33 + c] * G2 + rhi[i0 * 33 + c] * H2
              + rlo[i1 * 33 + c] * G0 + rhi[i1 * 33 + c] * H0;
        }
        out[(b * 512 + n) * 512 + m0 + c] = v;
    }
}

// ---------------------------------------------------------------------------
extern "C" void kernel_launch(void* const* d_in, const int* in_sizes, int n_in,
                              void* d_out, int out_size) {
    (void)in_sizes; (void)n_in; (void)out_size;
    const float* x = (const float*)d_in[0];

    const int dwt_smem  = (512 * 33 + 257 * 33) * 4;
    const int idwt_smem = (258 * 33 + 2 * 257 * 33) * 4;
    const int gemm_smem = (2 * 128 * 36 + 2 * 32 * 72) * 4;   // 55296 B
    const int mix_smem  = (4 * 2048 + 6 * 2048) * 4;          // 81920 B
    cudaFuncSetAttribute(dwt_fused,     cudaFuncAttributeMaxDynamicSharedMemorySize, dwt_smem);
    cudaFuncSetAttribute(idwt_fused,    cudaFuncAttributeMaxDynamicSharedMemorySize, idwt_smem);
    cudaFuncSetAttribute(fwd_gemm_tf32, cudaFuncAttributeMaxDynamicSharedMemorySize, gemm_smem);
    cudaFuncSetAttribute(inv_gemm_tf32, cudaFuncAttributeMaxDynamicSharedMemorySize, gemm_smem);
    cudaFuncSetAttribute(mix_kernel,    cudaFuncAttributeMaxDynamicSharedMemorySize, mix_smem);

    prep_basis<<<(N1 * 64 + N2 * 64 + 255) / 256, 256>>>();
    pack_weights<<<2048, 256>>>(
        (const float*)d_in[1],  (const float*)d_in[2],
        (const float*)d_in[3],  (const float*)d_in[4],
        (const float*)d_in[5],  (const float*)d_in[6],
        (const float*)d_in[7],  (const float*)d_in[8],
        (const float*)d_in[9],  (const float*)d_in[10],
        (const float*)d_in[11], (const float*)d_in[12],
        (const float*)d_in[13], (const float*)d_in[14]);

    dwt_fused<<<dim3(16, 32), 256, dwt_smem>>>(x);
    fwd_gemm_tf32<<<dim3(1, 128, 4), 256, gemm_smem>>>();
    mix_kernel<<<512, 256, mix_smem>>>();
    inv_gemm_tf32<<<dim3(8, 128, 2), 256, gemm_smem>>>();
    idwt_fused<<<dim3(16, 32), 256, idwt_smem>>>((float*)d_out);
}